// round 3
// baseline (speedup 1.0000x reference)
#include <cuda_runtime.h>

// ---------------------------------------------------------------------------
// MWDLSTMGCT: only the L->L wavelet path + LSTM3 are live (output = last time
// index of concat == s3 final h). Pipeline:
//   GEMM1: sig(x @ W1L^T + b1L) -> avgpool2 -> xl1 (256x512)
//   GEMM2: sig(xl1 @ W2L^T + b2L) -> avgpool2 -> xl2 (256x256)
//   LSTM3: T=256 steps, H=100, scalar input per step
//   out[b] = h_final[b] . Wout + bout
// ---------------------------------------------------------------------------

#define BATCH 256
#define HID   100
#define G4    400
#define T3    256

__device__ float g_xl1[BATCH * 512];
__device__ float g_xl2[BATCH * 256];

__device__ __forceinline__ float sigf(float x) {
    return 1.0f / (1.0f + __expf(-x));
}

__device__ __forceinline__ float tanh_fast(float x) {
    float xc = fminf(fmaxf(x, -15.0f), 15.0f);
    float e  = __expf(2.0f * xc);
    return __fdividef(e - 1.0f, e + 1.0f);
}

// packed f32x2 FMA (Blackwell; only reachable via PTX)
__device__ __forceinline__ unsigned long long fma2(unsigned long long a,
                                                   unsigned long long b,
                                                   unsigned long long c) {
    unsigned long long d;
    asm("fma.rn.f32x2 %0, %1, %2, %3;" : "=l"(d) : "l"(a), "l"(b), "l"(c));
    return d;
}

__device__ __forceinline__ float2 unpack2(unsigned long long a) {
    float2 r;
    asm("mov.b64 {%0, %1}, %2;" : "=f"(r.x), "=f"(r.y) : "l"(a));
    return r;
}

// ---------------------------------------------------------------------------
// out_pooled[M x N/2] = avgpool2( sigmoid( A[MxK] @ W[NxK]^T + bias[N] ) )
// BM=32, BN=64, BK=32, 128 threads, 4x4 micro-tile per thread.
// ---------------------------------------------------------------------------
__global__ __launch_bounds__(128)
void gemm_sig_pool(const float* __restrict__ A, const float* __restrict__ W,
                   const float* __restrict__ bias, float* __restrict__ out,
                   int K, int N) {
    const int BM = 32, BN = 64, BK = 32;
    __shared__ float As[BM][BK + 1];
    __shared__ float Ws[BN][BK + 1];

    int tid = threadIdx.x;          // 0..127
    int tx = tid & 15;              // 0..15  -> n group
    int ty = tid >> 4;              // 0..7   -> m group
    int m0 = blockIdx.x * BM;
    int n0 = blockIdx.y * BN;

    float acc[4][4];
#pragma unroll
    for (int i = 0; i < 4; i++)
#pragma unroll
        for (int j = 0; j < 4; j++) acc[i][j] = 0.0f;

    int lk = tid & 31;              // k within tile
    int lr = tid >> 5;              // 0..3

    for (int k0 = 0; k0 < K; k0 += BK) {
#pragma unroll
        for (int i = 0; i < 8; i++) {           // 32 A rows
            int r = lr + i * 4;
            As[r][lk] = A[(m0 + r) * K + k0 + lk];
        }
#pragma unroll
        for (int i = 0; i < 16; i++) {          // 64 W rows
            int r = lr + i * 4;
            Ws[r][lk] = W[(n0 + r) * K + k0 + lk];
        }
        __syncthreads();

#pragma unroll
        for (int k = 0; k < BK; k++) {
            float a[4], w[4];
#pragma unroll
            for (int i = 0; i < 4; i++) a[i] = As[ty * 4 + i][k];
#pragma unroll
            for (int j = 0; j < 4; j++) w[j] = Ws[tx * 4 + j][k];
#pragma unroll
            for (int i = 0; i < 4; i++)
#pragma unroll
                for (int j = 0; j < 4; j++) acc[i][j] += a[i] * w[j];
        }
        __syncthreads();
    }

    int halfN = N >> 1;
#pragma unroll
    for (int i = 0; i < 4; i++) {
        int m = m0 + ty * 4 + i;
#pragma unroll
        for (int j = 0; j < 2; j++) {
            int n = n0 + tx * 4 + j * 2;
            float v0 = sigf(acc[i][j * 2]     + bias[n]);
            float v1 = sigf(acc[i][j * 2 + 1] + bias[n + 1]);
            out[m * halfN + (n >> 1)] = 0.5f * (v0 + v1);
        }
    }
}

// ---------------------------------------------------------------------------
// LSTM3: 128 blocks x 2 batch elements, 416 threads.
// Thread t < 400 owns gate-unit t: Whh row t kept in 50 packed f32x2 regs.
// Per step: matvec z = Whh @ h (+x*Wih+b), then threads 0..99 do gate update.
// ---------------------------------------------------------------------------
__global__ __launch_bounds__(416, 1)
void lstm_kernel(const float* __restrict__ xin,   // [BATCH, 256] = g_xl2
                 const float* __restrict__ Wih,   // [400,1]
                 const float* __restrict__ Whh,   // [400,100]
                 const float* __restrict__ b,     // [400]
                 const float* __restrict__ Wout,  // [1,100]
                 const float* __restrict__ bout,  // [1]
                 float* __restrict__ out) {       // [BATCH]
    __shared__ alignas(16) float hA[104];
    __shared__ alignas(16) float hB[104];
    __shared__ float zA[G4];
    __shared__ float zB[G4];
    __shared__ float xA[T3];
    __shared__ float xB[T3];
    __shared__ float red[212];

    int t  = threadIdx.x;
    int bA = blockIdx.x * 2;
    int bB = bA + 1;

    // preload per-element input sequences
    for (int i = t; i < T3; i += 416) {
        xA[i] = xin[bA * T3 + i];
        xB[i] = xin[bB * T3 + i];
    }
    if (t < 104) { hA[t] = 0.0f; hB[t] = 0.0f; }

    // weight-stationary: Whh row t in registers (packed pairs)
    unsigned long long wp[50];
    float wih_t = 0.0f, b_t = 0.0f;
    if (t < G4) {
        const unsigned long long* wr =
            (const unsigned long long*)(Whh + t * HID);   // rows are 400B -> 16B aligned
#pragma unroll
        for (int k = 0; k < 50; k++) wp[k] = wr[k];
        wih_t = Wih[t];
        b_t   = b[t];
    }

    float cA = 0.0f, cB = 0.0f;
    const unsigned long long* h64A = (const unsigned long long*)hA;
    const unsigned long long* h64B = (const unsigned long long*)hB;

    for (int s = 0; s < T3; s++) {
        __syncthreads();          // h ready for this step
        if (t < G4) {
            unsigned long long a0 = 0ull, a1 = 0ull, d0 = 0ull, d1 = 0ull;
#pragma unroll
            for (int k = 0; k < 50; k += 2) {
                a0 = fma2(wp[k],     h64A[k],     a0);
                a1 = fma2(wp[k + 1], h64A[k + 1], a1);
                d0 = fma2(wp[k],     h64B[k],     d0);
                d1 = fma2(wp[k + 1], h64B[k + 1], d1);
            }
            float2 fa0 = unpack2(a0), fa1 = unpack2(a1);
            float2 fb0 = unpack2(d0), fb1 = unpack2(d1);
            zA[t] = fa0.x + fa0.y + fa1.x + fa1.y + xA[s] * wih_t + b_t;
            zB[t] = fb0.x + fb0.y + fb1.x + fb1.y + xB[s] * wih_t + b_t;
        }
        __syncthreads();          // z complete
        if (t < HID) {
            float iv = sigf(zA[t]);
            float fv = sigf(zA[t + 100]);
            float gv = tanh_fast(zA[t + 200]);
            float ov = sigf(zA[t + 300]);
            cA = fv * cA + iv * gv;
            hA[t] = ov * tanh_fast(cA);

            iv = sigf(zB[t]);
            fv = sigf(zB[t + 100]);
            gv = tanh_fast(zB[t + 200]);
            ov = sigf(zB[t + 300]);
            cB = fv * cB + iv * gv;
            hB[t] = ov * tanh_fast(cB);
        }
    }

    __syncthreads();
    if (t < HID) {
        float w = Wout[t];
        red[t]       = hA[t] * w;
        red[t + 106] = hB[t] * w;
    }
    __syncthreads();
    if (t == 0) {
        float s1 = 0.0f, s2 = 0.0f;
        for (int j = 0; j < HID; j++) { s1 += red[j]; s2 += red[j + 106]; }
        out[bA] = s1 + bout[0];
        out[bB] = s2 + bout[0];
    }
}

// ---------------------------------------------------------------------------
extern "C" void kernel_launch(void* const* d_in, const int* in_sizes, int n_in,
                              void* d_out, int out_size) {
    const float* x    = (const float*)d_in[0];
    const float* W1L  = (const float*)d_in[3];
    const float* b1L  = (const float*)d_in[4];
    const float* W2L  = (const float*)d_in[7];
    const float* b2L  = (const float*)d_in[8];
    const float* Wih3 = (const float*)d_in[15];
    const float* Whh3 = (const float*)d_in[16];
    const float* b3   = (const float*)d_in[17];
    const float* Wout = (const float*)d_in[18];
    const float* bout = (const float*)d_in[19];
    float* out = (float*)d_out;

    float* xl1;
    float* xl2;
    cudaGetSymbolAddress((void**)&xl1, g_xl1);
    cudaGetSymbolAddress((void**)&xl2, g_xl2);

    // Layer 1: x(256x1024) @ W1L^T(1024x1024) -> sig -> pool -> xl1(256x512)
    gemm_sig_pool<<<dim3(256 / 32, 1024 / 64), 128>>>(x, W1L, b1L, xl1, 1024, 1024);
    // Layer 2: xl1(256x512) @ W2L^T(512x512) -> sig -> pool -> xl2(256x256)
    gemm_sig_pool<<<dim3(256 / 32, 512 / 64), 128>>>(xl1, W2L, b2L, xl2, 512, 512);
    // LSTM3 + output projection
    lstm_kernel<<<BATCH / 2, 416>>>(xl2, Wih3, Whh3, b3, Wout, bout, out);
}

// round 6
// speedup vs baseline: 1.1598x; 1.1598x over previous
#include <cuda_runtime.h>

// ---------------------------------------------------------------------------
// MWDLSTMGCT: only the L->L wavelet path + LSTM3 are live (output = last time
// index of concat == s3 final h).
//   GEMM1: sig(x @ W1L^T + b1L) -> avgpool2 -> xl1 (256x512)
//   GEMM2: sig(xl1 @ W2L^T + b2L) -> avgpool2 -> xl2 (256x256)
//   LSTM3: T=256 steps, H=100, scalar input per step
//   out[b] = h_final[b] . Wout + bout
// ---------------------------------------------------------------------------

#define BATCH 256
#define HID   100
#define G4    400
#define T3    256

__device__ float g_xl1[BATCH * 512];
__device__ float g_xl2[BATCH * 256];

__device__ __forceinline__ float sigf(float x) {
    return 1.0f / (1.0f + __expf(-x));
}

__device__ __forceinline__ float tanh_fast(float x) {
    float xc = fminf(fmaxf(x, -15.0f), 15.0f);
    float e  = __expf(2.0f * xc);
    return __fdividef(e - 1.0f, e + 1.0f);
}

// packed f32x2 FMA (Blackwell; only reachable via PTX)
__device__ __forceinline__ unsigned long long fma2(unsigned long long a,
                                                   unsigned long long b,
                                                   unsigned long long c) {
    unsigned long long d;
    asm("fma.rn.f32x2 %0, %1, %2, %3;" : "=l"(d) : "l"(a), "l"(b), "l"(c));
    return d;
}

__device__ __forceinline__ float2 unpack2(unsigned long long a) {
    float2 r;
    asm("mov.b64 {%0, %1}, %2;" : "=f"(r.x), "=f"(r.y) : "l"(a));
    return r;
}

// ---------------------------------------------------------------------------
// out_pooled[M x N/2] = avgpool2( sigmoid( A[MxK] @ W[NxK]^T + bias[N] ) )
// BM=16, BN=64, BK=32, 128 threads, 2x4 micro-tile per thread.
// Grid for GEMM1: 16x16 = 256 blocks -> ~2 blocks/SM, 8 warps/SM.
// ---------------------------------------------------------------------------
__global__ __launch_bounds__(128)
void gemm_sig_pool(const float* __restrict__ A, const float* __restrict__ W,
                   const float* __restrict__ bias, float* __restrict__ out,
                   int K, int N) {
    const int BM = 16, BN = 64, BK = 32;
    __shared__ float As[BM][BK + 1];
    __shared__ float Ws[BN][BK + 1];

    int tid = threadIdx.x;          // 0..127
    int tx = tid & 15;              // 0..15  -> n group (4 cols)
    int ty = tid >> 4;              // 0..7   -> m group (2 rows)
    int m0 = blockIdx.x * BM;
    int n0 = blockIdx.y * BN;

    float acc[2][4];
#pragma unroll
    for (int i = 0; i < 2; i++)
#pragma unroll
        for (int j = 0; j < 4; j++) acc[i][j] = 0.0f;

    int lk = tid & 31;              // k within tile
    int lr = tid >> 5;              // 0..3

    for (int k0 = 0; k0 < K; k0 += BK) {
#pragma unroll
        for (int i = 0; i < 4; i++) {           // 16 A rows
            int r = lr + i * 4;
            As[r][lk] = A[(m0 + r) * K + k0 + lk];
        }
#pragma unroll
        for (int i = 0; i < 16; i++) {          // 64 W rows
            int r = lr + i * 4;
            Ws[r][lk] = W[(n0 + r) * K + k0 + lk];
        }
        __syncthreads();

#pragma unroll
        for (int k = 0; k < BK; k++) {
            float a[2], w[4];
#pragma unroll
            for (int i = 0; i < 2; i++) a[i] = As[ty * 2 + i][k];
#pragma unroll
            for (int j = 0; j < 4; j++) w[j] = Ws[tx * 4 + j][k];
#pragma unroll
            for (int i = 0; i < 2; i++)
#pragma unroll
                for (int j = 0; j < 4; j++) acc[i][j] += a[i] * w[j];
        }
        __syncthreads();
    }

    int halfN = N >> 1;
#pragma unroll
    for (int i = 0; i < 2; i++) {
        int m = m0 + ty * 2 + i;
#pragma unroll
        for (int j = 0; j < 2; j++) {
            int n = n0 + tx * 4 + j * 2;
            float v0 = sigf(acc[i][j * 2]     + bias[n]);
            float v1 = sigf(acc[i][j * 2 + 1] + bias[n + 1]);
            out[m * halfN + (n >> 1)] = 0.5f * (v0 + v1);
        }
    }
}

// ---------------------------------------------------------------------------
// LSTM3: 128 blocks x 2 batch elements, 416 threads (13 warps).
// Thread t < 400 owns gate-unit t for BOTH elems: Whh row t in 50 packed
// f32x2 registers, h read via LDS.128 (25 per elem per step).
// Gate phase: elem A on threads 0..99 (warps 0-3), elem B on threads
// 128..227 (warps 4-7) -> the two nonlinearity chains run in parallel warps.
// ---------------------------------------------------------------------------
__global__ __launch_bounds__(416, 1)
void lstm_kernel(const float* __restrict__ xin,   // [BATCH, 256] = g_xl2
                 const float* __restrict__ Wih,   // [400,1]
                 const float* __restrict__ Whh,   // [400,100]
                 const float* __restrict__ b,     // [400]
                 const float* __restrict__ Wout,  // [1,100]
                 const float* __restrict__ bout,  // [1]
                 float* __restrict__ out) {       // [BATCH]
    __shared__ alignas(16) float hA[104];
    __shared__ alignas(16) float hB[104];
    __shared__ float zA[G4];
    __shared__ float zB[G4];
    __shared__ float xA[T3];
    __shared__ float xB[T3];
    __shared__ float red[228];

    int t  = threadIdx.x;
    int bA = blockIdx.x * 2;
    int bB = bA + 1;

    // preload per-element input sequences
    for (int i = t; i < T3; i += 416) {
        xA[i] = xin[bA * T3 + i];
        xB[i] = xin[bB * T3 + i];
    }
    if (t < 104) { hA[t] = 0.0f; hB[t] = 0.0f; }

    // weight-stationary: Whh row t in registers (packed pairs)
    unsigned long long wp[50];
    float wih_t = 0.0f, b_t = 0.0f;
    if (t < G4) {
        const unsigned long long* wr =
            (const unsigned long long*)(Whh + t * HID);   // rows 400B -> 16B aligned
#pragma unroll
        for (int k = 0; k < 50; k++) wp[k] = wr[k];
        wih_t = Wih[t];
        b_t   = b[t];
    }

    float c = 0.0f;                          // cA for t<100, cB for t in [128,228)
    int tb = t - 128;
    const ulonglong2* h128A = (const ulonglong2*)hA;
    const ulonglong2* h128B = (const ulonglong2*)hB;

    for (int s = 0; s < T3; s++) {
        __syncthreads();          // h ready for this step
        if (t < G4) {
            unsigned long long a0 = 0ull, a1 = 0ull, d0 = 0ull, d1 = 0ull;
#pragma unroll
            for (int k = 0; k < 25; k++) {
                ulonglong2 ha = h128A[k];
                ulonglong2 hb = h128B[k];
                a0 = fma2(wp[2 * k],     ha.x, a0);
                a1 = fma2(wp[2 * k + 1], ha.y, a1);
                d0 = fma2(wp[2 * k],     hb.x, d0);
                d1 = fma2(wp[2 * k + 1], hb.y, d1);
            }
            float gbase = fmaf(xA[s], wih_t, b_t);
            float gbaseB = fmaf(xB[s], wih_t, b_t);
            float2 fa0 = unpack2(a0), fa1 = unpack2(a1);
            float2 fb0 = unpack2(d0), fb1 = unpack2(d1);
            zA[t] = (fa0.x + fa0.y) + (fa1.x + fa1.y) + gbase;
            zB[t] = (fb0.x + fb0.y) + (fb1.x + fb1.y) + gbaseB;
        }
        __syncthreads();          // z complete
        if (t < HID) {
            float iv = sigf(zA[t]);
            float fv = sigf(zA[t + 100]);
            float gv = tanh_fast(zA[t + 200]);
            float ov = sigf(zA[t + 300]);
            c = fv * c + iv * gv;
            hA[t] = ov * tanh_fast(c);
        } else if (tb >= 0 && tb < HID) {
            float iv = sigf(zB[tb]);
            float fv = sigf(zB[tb + 100]);
            float gv = tanh_fast(zB[tb + 200]);
            float ov = sigf(zB[tb + 300]);
            c = fv * c + iv * gv;
            hB[tb] = ov * tanh_fast(c);
        }
    }

    __syncthreads();
    if (t < HID) {
        red[t] = hA[t] * Wout[t];
    } else if (tb >= 0 && tb < HID) {
        red[tb + 114] = hB[tb] * Wout[tb];
    }
    __syncthreads();
    if (t == 0) {
        float s1 = 0.0f;
        for (int j = 0; j < HID; j++) s1 += red[j];
        out[bA] = s1 + bout[0];
    } else if (t == 128) {
        float s2 = 0.0f;
        for (int j = 0; j < HID; j++) s2 += red[j + 114];
        out[bB] = s2 + bout[0];
    }
}

// ---------------------------------------------------------------------------
extern "C" void kernel_launch(void* const* d_in, const int* in_sizes, int n_in,
                              void* d_out, int out_size) {
    const float* x    = (const float*)d_in[0];
    const float* W1L  = (const float*)d_in[3];
    const float* b1L  = (const float*)d_in[4];
    const float* W2L  = (const float*)d_in[7];
    const float* b2L  = (const float*)d_in[8];
    const float* Wih3 = (const float*)d_in[15];
    const float* Whh3 = (const float*)d_in[16];
    const float* b3   = (const float*)d_in[17];
    const float* Wout = (const float*)d_in[18];
    const float* bout = (const float*)d_in[19];
    float* out = (float*)d_out;

    float* xl1;
    float* xl2;
    cudaGetSymbolAddress((void**)&xl1, g_xl1);
    cudaGetSymbolAddress((void**)&xl2, g_xl2);

    // Layer 1: x(256x1024) @ W1L^T(1024x1024) -> sig -> pool -> xl1(256x512)
    gemm_sig_pool<<<dim3(256 / 16, 1024 / 64), 128>>>(x, W1L, b1L, xl1, 1024, 1024);
    // Layer 2: xl1(256x512) @ W2L^T(512x512) -> sig -> pool -> xl2(256x256)
    gemm_sig_pool<<<dim3(256 / 16, 512 / 64), 128>>>(xl1, W2L, b2L, xl2, 512, 512);
    // LSTM3 + output projection
    lstm_kernel<<<BATCH / 2, 416>>>(xl2, Wih3, Whh3, b3, Wout, bout, out);
}